// round 3
// baseline (speedup 1.0000x reference)
#include <cuda_runtime.h>
#include <math_constants.h>

// Problem constants
#define BB 2
#define S  2048
#define DD 1024
#define H  16
#define HD 64
#define BH (BB*H)     // 32
#define MROWS (BB*S)  // 4096
#define MASK_N (BB*S*S)  // 8,388,608

// Scratch (device globals: allocation-free)
__device__ float g_q[BH * S * HD];
__device__ float g_k[BH * S * HD];
__device__ float g_v[BH * S * HD];
__device__ unsigned char g_mask_u8[MASK_N];
__device__ int g_mask_mode;  // 0=uint8/bool, 1=int32, 2=float32
__device__ float g_rowsum[BH * S];
__device__ float g_attn_scratch[(size_t)BH * S * S]; // fallback if d_out only holds ctx

// ---------------------------------------------------------------------------
// Fast exp on the FMA pipe (avoids MUFU throughput wall: 134M exps needed).
// |rel err| ~1e-7 for |x| <= 87.
// ---------------------------------------------------------------------------
__device__ __forceinline__ float fast_exp(float x) {
    x = fminf(fmaxf(x, -87.0f), 87.0f);
    float t = x * 1.4426950408889634f;       // x / ln2
    float r = rintf(t);
    float y = fmaf(-r, 0.693145751953125f, x);        // ln2 hi
    y = fmaf(-r, 1.428606765330187045e-6f, y);        // ln2 lo
    float p = 1.3888888888888889e-3f;                 // 1/720
    p = fmaf(p, y, 8.3333333333333333e-3f);           // 1/120
    p = fmaf(p, y, 4.1666666666666664e-2f);           // 1/24
    p = fmaf(p, y, 1.6666666666666666e-1f);           // 1/6
    p = fmaf(p, y, 5.0e-1f);
    p = fmaf(p, y, 1.0f);
    p = fmaf(p, y, 1.0f);
    float sc = __int_as_float(((int)r + 127) << 23);  // 2^r
    return p * sc;
}

// ---------------------------------------------------------------------------
// Mask dtype detection + conversion (unchanged from R2; proven correct)
// ---------------------------------------------------------------------------
__global__ void detect_mask_kernel(const unsigned int* __restrict__ w) {
    __shared__ int s_int, s_float;
    if (threadIdx.x == 0) { s_int = 1; s_float = 1; }
    __syncthreads();
    int li = 1, lf = 1;
    for (int i = threadIdx.x; i < 2048; i += 256) {
        unsigned int x = w[i];
        if (x != 0u && x != 1u) li = 0;
        if (x != 0u && x != 0x3f800000u) lf = 0;
    }
    if (!li) atomicAnd(&s_int, 0);
    if (!lf) atomicAnd(&s_float, 0);
    __syncthreads();
    if (threadIdx.x == 0) g_mask_mode = s_int ? 1 : (s_float ? 2 : 0);
}

__global__ void convert_mask_kernel(const void* __restrict__ mraw,
                                    unsigned char* __restrict__ mu8) {
    int i = blockIdx.x * blockDim.x + threadIdx.x;
    if (i >= MASK_N) return;
    int mode = g_mask_mode;
    unsigned char v;
    if (mode == 0)      v = ((const unsigned char*)mraw)[i];
    else if (mode == 1) v = (unsigned char)(((const int*)mraw)[i] != 0);
    else                v = (unsigned char)(((const float*)mraw)[i] != 0.0f);
    mu8[i] = v;
}

// ---------------------------------------------------------------------------
// All 3 projections in one launch (z = 0,1,2). 128x128 tile, K-step 32,
// float4 everywhere, 8x8 micro-tile with contiguous-4 fragments.
// Writes head-split layout out[(b*H+h)*S*HD + s*HD + d].
// ---------------------------------------------------------------------------
__global__ void __launch_bounds__(256, 2)
proj3_kernel(const float* __restrict__ X0, const float* __restrict__ X1,
             const float* __restrict__ X2,
             const float* __restrict__ W0, const float* __restrict__ W1,
             const float* __restrict__ W2,
             const float* __restrict__ B0, const float* __restrict__ B1,
             const float* __restrict__ B2,
             float* __restrict__ O0, float* __restrict__ O1, float* __restrict__ O2) {
    const float *X, *W, *Bv; float* O;
    if (blockIdx.z == 0)      { X = X0; W = W0; Bv = B0; O = O0; }
    else if (blockIdx.z == 1) { X = X1; W = W1; Bv = B1; O = O1; }
    else                      { X = X2; W = W2; Bv = B2; O = O2; }

    __shared__ float sA[32][132];
    __shared__ float sB[32][132];
    const int tid = threadIdx.x;
    const int tx = tid & 15, ty = tid >> 4;
    const int m0 = blockIdx.y * 128;
    const int n0 = blockIdx.x * 128;

    float acc[8][8];
#pragma unroll
    for (int i = 0; i < 8; i++)
#pragma unroll
        for (int j = 0; j < 8; j++) acc[i][j] = 0.0f;

    const int lrow = tid >> 3;       // 0..31 (+32 per it)
    const int lc4  = tid & 7;        // float4 index within 32-wide K slab

    for (int k0 = 0; k0 < DD; k0 += 32) {
#pragma unroll
        for (int it = 0; it < 4; it++) {
            int row = lrow + it * 32;
            float4 va = *(const float4*)(X + (size_t)(m0 + row) * DD + k0 + lc4 * 4);
            sA[lc4 * 4 + 0][row] = va.x; sA[lc4 * 4 + 1][row] = va.y;
            sA[lc4 * 4 + 2][row] = va.z; sA[lc4 * 4 + 3][row] = va.w;
            float4 vb = *(const float4*)(W + (size_t)(n0 + row) * DD + k0 + lc4 * 4);
            sB[lc4 * 4 + 0][row] = vb.x; sB[lc4 * 4 + 1][row] = vb.y;
            sB[lc4 * 4 + 2][row] = vb.z; sB[lc4 * 4 + 3][row] = vb.w;
        }
        __syncthreads();
#pragma unroll 8
        for (int kk = 0; kk < 32; kk++) {
            float4 a0 = *(const float4*)&sA[kk][4 * ty];
            float4 a1 = *(const float4*)&sA[kk][4 * ty + 64];
            float4 b0 = *(const float4*)&sB[kk][4 * tx];
            float4 b1 = *(const float4*)&sB[kk][4 * tx + 64];
            float a[8] = {a0.x, a0.y, a0.z, a0.w, a1.x, a1.y, a1.z, a1.w};
            float b[8] = {b0.x, b0.y, b0.z, b0.w, b1.x, b1.y, b1.z, b1.w};
#pragma unroll
            for (int i = 0; i < 8; i++)
#pragma unroll
                for (int j = 0; j < 8; j++) acc[i][j] = fmaf(a[i], b[j], acc[i][j]);
        }
        __syncthreads();
    }

    // Epilogue: bias + head-split float4 stores
    float4 bl = *(const float4*)&Bv[n0 + 4 * tx];
    float4 bh4 = *(const float4*)&Bv[n0 + 4 * tx + 64];
    int c_lo = n0 + 4 * tx, c_hi = c_lo + 64;
    int h_lo = c_lo >> 6, d_lo = c_lo & 63;
    int h_hi = c_hi >> 6, d_hi = c_hi & 63;
#pragma unroll
    for (int i = 0; i < 8; i++) {
        int r = m0 + 4 * ty + (i & 3) + ((i >> 2) << 6);
        int b_ = r >> 11, s = r & (S - 1);
        float4 v0 = make_float4(acc[i][0] + bl.x, acc[i][1] + bl.y,
                                acc[i][2] + bl.z, acc[i][3] + bl.w);
        float4 v1 = make_float4(acc[i][4] + bh4.x, acc[i][5] + bh4.y,
                                acc[i][6] + bh4.z, acc[i][7] + bh4.w);
        *(float4*)&O[(((size_t)(b_ * H + h_lo)) * S + s) * HD + d_lo] = v0;
        *(float4*)&O[(((size_t)(b_ * H + h_hi)) * S + s) * HD + d_hi] = v1;
    }
}

// ---------------------------------------------------------------------------
// Scores + mask + EXP fused: attn_e[bh,q,k] = mask ? 0 : exp((Q.K)/8)
// Also accumulates per-row sums (warp reduce + atomicAdd).
// Tile: 32 q x 128 k, 256 threads, 4x4 per thread.
// ---------------------------------------------------------------------------
__global__ void scores_kernel(const float* __restrict__ Q, const float* __restrict__ K,
                              const unsigned char* __restrict__ mask,
                              float* __restrict__ attn, float* __restrict__ rowsum) {
    __shared__ float sQ[32][64];
    __shared__ float sK[64][137];
    const int tid = threadIdx.x;
    const int tx = tid & 31, ty = tid >> 5;
    const int k0 = blockIdx.x * 128;
    const int q0 = blockIdx.y * 32;
    const int bh = blockIdx.z;

    const float* Qb = Q + (size_t)bh * S * HD;
    const float* Kb = K + (size_t)bh * S * HD;

#pragma unroll
    for (int it = 0; it < 8; it++) {
        int t = tid + it * 256;
        int q = t >> 6, d = t & 63;
        sQ[q][d] = Qb[(size_t)(q0 + q) * HD + d];
    }
#pragma unroll
    for (int it = 0; it < 32; it++) {
        int t = tid + it * 256;
        int k = t >> 6, d = t & 63;
        sK[d][k] = Kb[(size_t)(k0 + k) * HD + d];
    }
    __syncthreads();

    float acc[4][4];
#pragma unroll
    for (int i = 0; i < 4; i++)
#pragma unroll
        for (int j = 0; j < 4; j++) acc[i][j] = 0.0f;

#pragma unroll 16
    for (int d = 0; d < 64; d++) {
        float a[4], b[4];
#pragma unroll
        for (int i = 0; i < 4; i++) a[i] = sQ[ty + 8 * i][d];
#pragma unroll
        for (int j = 0; j < 4; j++) b[j] = sK[d][tx + 32 * j];
#pragma unroll
        for (int i = 0; i < 4; i++)
#pragma unroll
            for (int j = 0; j < 4; j++) acc[i][j] = fmaf(a[i], b[j], acc[i][j]);
    }

    // torch mask.repeat(H,1,1): head index bh uses mask[bh % B]
    const unsigned char* mb = mask + (size_t)(bh & (BB - 1)) * S * S;
    float* ab = attn + (size_t)bh * S * S;
#pragma unroll
    for (int i = 0; i < 4; i++) {
        int q = q0 + ty + 8 * i;
        float rs = 0.0f;
#pragma unroll
        for (int j = 0; j < 4; j++) {
            int k = k0 + tx + 32 * j;
            size_t idx = (size_t)q * S + k;
            float e = mb[idx] ? 0.0f : fast_exp(acc[i][j] * 0.125f);
            ab[idx] = e;
            rs += e;
        }
        // warp reduce across tx (warp == fixed ty)
#pragma unroll
        for (int o = 16; o > 0; o >>= 1) rs += __shfl_xor_sync(0xffffffffu, rs, o);
        if (tx == 0) atomicAdd(&rowsum[bh * S + q], rs);
    }
}

// ---------------------------------------------------------------------------
// AV + normalize fused: attn /= rowsum (written back), ctx = attn @ V.
// Block: 128 q x 64 d, K-step 32. 256 threads: 16q x 2d per thread.
// ---------------------------------------------------------------------------
__global__ void av_kernel(float* __restrict__ attn, const float* __restrict__ V,
                          const float* __restrict__ rowsum, float* __restrict__ out) {
    __shared__ float sA[128][33];
    __shared__ float sV[32][64];
    __shared__ float rr[128];
    const int tid = threadIdx.x;
    const int tx = tid & 31, ty = tid >> 5;
    const int q0 = blockIdx.x * 128;
    const int bh = blockIdx.y;

    float* ab = attn + (size_t)bh * S * S;
    const float* Vb = V + (size_t)bh * S * HD;

    if (tid < 128) rr[tid] = 1.0f / rowsum[bh * S + q0 + tid];
    __syncthreads();

    float acc[16][2];
#pragma unroll
    for (int i = 0; i < 16; i++) { acc[i][0] = 0.0f; acc[i][1] = 0.0f; }

    for (int k0 = 0; k0 < S; k0 += 32) {
#pragma unroll
        for (int it = 0; it < 16; it++) {  // 128*32 / 256
            int t = tid + it * 256;
            int q = t >> 5, k = t & 31;
            size_t idx = (size_t)(q0 + q) * S + k0 + k;
            float v = ab[idx] * rr[q];
            sA[q][k] = v;
            ab[idx] = v;                  // write normalized attn (final output)
        }
#pragma unroll
        for (int it = 0; it < 8; it++) {   // 32*64 / 256
            int t = tid + it * 256;
            int k = t >> 6, d = t & 63;
            sV[k][d] = Vb[(size_t)(k0 + k) * HD + d];
        }
        __syncthreads();
#pragma unroll 8
        for (int k = 0; k < 32; k++) {
            float b0 = sV[k][tx];
            float b1 = sV[k][tx + 32];
#pragma unroll
            for (int i = 0; i < 16; i++) {
                float a = sA[ty + 8 * i][k];
                acc[i][0] = fmaf(a, b0, acc[i][0]);
                acc[i][1] = fmaf(a, b1, acc[i][1]);
            }
        }
        __syncthreads();
    }

    const int b = bh >> 4, h = bh & 15;
#pragma unroll
    for (int i = 0; i < 16; i++) {
        int s = q0 + ty + 8 * i;
        size_t base = ((size_t)(b * S + s)) * DD + h * HD;
        out[base + tx]      = acc[i][0];
        out[base + tx + 32] = acc[i][1];
    }
}

// ---------------------------------------------------------------------------
extern "C" void kernel_launch(void* const* d_in, const int* in_sizes, int n_in,
                              void* d_out, int out_size) {
    const float* query = (const float*)d_in[0];
    const float* key   = (const float*)d_in[1];
    const float* value = (const float*)d_in[2];
    const void*  mask  = d_in[3];
    const float* Wq = (const float*)d_in[4];
    const float* bq = (const float*)d_in[5];
    const float* Wk = (const float*)d_in[6];
    const float* bk = (const float*)d_in[7];
    const float* Wv = (const float*)d_in[8];
    const float* bv = (const float*)d_in[9];

    float* ctx = (float*)d_out;

    float *qp, *kp, *vp, *rowsum, *attn_fallback;
    unsigned char* mu8;
    cudaGetSymbolAddress((void**)&qp, g_q);
    cudaGetSymbolAddress((void**)&kp, g_k);
    cudaGetSymbolAddress((void**)&vp, g_v);
    cudaGetSymbolAddress((void**)&mu8, g_mask_u8);
    cudaGetSymbolAddress((void**)&rowsum, g_rowsum);
    cudaGetSymbolAddress((void**)&attn_fallback, g_attn_scratch);

    const long long CTX_ELEMS  = (long long)BB * S * DD;            // 4,194,304
    const long long ATTN_ELEMS = (long long)BH * S * S;             // 134,217,728
    float* attn = ((long long)out_size >= CTX_ELEMS + ATTN_ELEMS)
                      ? (ctx + CTX_ELEMS) : attn_fallback;

    // Normalize mask to uint8 regardless of marshalled dtype
    detect_mask_kernel<<<1, 256>>>((const unsigned int*)mask);
    convert_mask_kernel<<<MASK_N / 256, 256>>>(mask, mu8);

    cudaMemsetAsync(rowsum, 0, BH * S * sizeof(float));

    proj3_kernel<<<dim3(DD / 128, MROWS / 128, 3), 256>>>(
        query, key, value, Wq, Wk, Wv, bq, bk, bv, qp, kp, vp);

    scores_kernel<<<dim3(S / 128, S / 32, BH), 256>>>(qp, kp, mu8, attn, rowsum);
    av_kernel<<<dim3(S / 128, BH), 256>>>(attn, vp, rowsum, ctx);
}

// round 4
// speedup vs baseline: 2.6140x; 2.6140x over previous
#include <cuda_runtime.h>
#include <cuda_bf16.h>
#include <mma.h>
#include <math_constants.h>

using namespace nvcuda;

// Problem constants
#define BB 2
#define S  2048
#define DD 1024
#define H  16
#define HD 64
#define BH (BB*H)       // 32
#define MROWS (BB*S)    // 4096
#define MASK_N (BB*S*S) // 8,388,608

// Scratch (device globals: allocation-free)
__device__ __nv_bfloat16 g_qh[BH * S * HD];
__device__ __nv_bfloat16 g_ql[BH * S * HD];
__device__ __nv_bfloat16 g_kh[BH * S * HD];
__device__ __nv_bfloat16 g_kl[BH * S * HD];
__device__ __nv_bfloat16 g_vh[BH * S * HD];
__device__ __nv_bfloat16 g_vl[BH * S * HD];
__device__ __nv_bfloat16 g_eh[(size_t)BH * S * S];   // exp hi
__device__ __nv_bfloat16 g_el[(size_t)BH * S * S];   // exp lo
__device__ float g_rowsum[BH * S];
__device__ unsigned char g_mask_u8[MASK_N];
__device__ int g_mask_mode;
__device__ float g_attn_scratch[(size_t)BH * S * S]; // fallback if d_out only holds ctx

// ---------------------------------------------------------------------------
__device__ __forceinline__ float fast_exp(float x) {
    x = fminf(fmaxf(x, -87.0f), 87.0f);
    float t = x * 1.4426950408889634f;
    float r = rintf(t);
    float y = fmaf(-r, 0.693145751953125f, x);
    y = fmaf(-r, 1.428606765330187045e-6f, y);
    float p = 1.3888888888888889e-3f;
    p = fmaf(p, y, 8.3333333333333333e-3f);
    p = fmaf(p, y, 4.1666666666666664e-2f);
    p = fmaf(p, y, 1.6666666666666666e-1f);
    p = fmaf(p, y, 5.0e-1f);
    p = fmaf(p, y, 1.0f);
    p = fmaf(p, y, 1.0f);
    float sc = __int_as_float(((int)r + 127) << 23);
    return p * sc;
}

__device__ __forceinline__ void split_bf(float x, __nv_bfloat16& h, __nv_bfloat16& l) {
    h = __float2bfloat16(x);
    l = __float2bfloat16(x - __bfloat162float(h));
}
__device__ __forceinline__ unsigned pack2(__nv_bfloat16 a, __nv_bfloat16 b) {
    __nv_bfloat162 t; t.x = a; t.y = b;
    return *(unsigned*)&t;
}
__device__ __forceinline__ float2 unpack2(unsigned u) {
    return __bfloat1622float2(*(__nv_bfloat162*)&u);
}

// ---------------------------------------------------------------------------
// Mask dtype detection + conversion (proven in R2/R3)
// ---------------------------------------------------------------------------
__global__ void detect_mask_kernel(const unsigned int* __restrict__ w) {
    __shared__ int s_int, s_float;
    if (threadIdx.x == 0) { s_int = 1; s_float = 1; }
    __syncthreads();
    int li = 1, lf = 1;
    for (int i = threadIdx.x; i < 2048; i += 256) {
        unsigned int x = w[i];
        if (x != 0u && x != 1u) li = 0;
        if (x != 0u && x != 0x3f800000u) lf = 0;
    }
    if (!li) atomicAnd(&s_int, 0);
    if (!lf) atomicAnd(&s_float, 0);
    __syncthreads();
    if (threadIdx.x == 0) g_mask_mode = s_int ? 1 : (s_float ? 2 : 0);
}

__global__ void convert_mask_kernel(const void* __restrict__ mraw,
                                    unsigned char* __restrict__ mu8) {
    int i = blockIdx.x * blockDim.x + threadIdx.x;
    if (i >= MASK_N) return;
    int mode = g_mask_mode;
    unsigned char v;
    if (mode == 0)      v = ((const unsigned char*)mraw)[i];
    else if (mode == 1) v = (unsigned char)(((const int*)mraw)[i] != 0);
    else                v = (unsigned char)(((const float*)mraw)[i] != 0.0f);
    mu8[i] = v;
}

// ---------------------------------------------------------------------------
// Projection (all 3 via z): C = X*W^T + bias, then *scale, split to bf16
// hi/lo, written head-split: out[(b*H+h)*S*HD + s*HD + d]. wmma 128x128 tile.
// ---------------------------------------------------------------------------
__global__ void __launch_bounds__(256, 2)
proj_wmma(const float* __restrict__ X0, const float* __restrict__ X1, const float* __restrict__ X2,
          const float* __restrict__ W0, const float* __restrict__ W1, const float* __restrict__ W2,
          const float* __restrict__ B0, const float* __restrict__ B1, const float* __restrict__ B2,
          __nv_bfloat16* __restrict__ Oh0, __nv_bfloat16* __restrict__ Ol0,
          __nv_bfloat16* __restrict__ Oh1, __nv_bfloat16* __restrict__ Ol1,
          __nv_bfloat16* __restrict__ Oh2, __nv_bfloat16* __restrict__ Ol2) {
    extern __shared__ char smraw[];
    __nv_bfloat16* sAh = (__nv_bfloat16*)smraw;        // [128][40]
    __nv_bfloat16* sAl = sAh + 128 * 40;
    __nv_bfloat16* sBh = sAl + 128 * 40;
    __nv_bfloat16* sBl = sBh + 128 * 40;
    float* sC = (float*)smraw;                         // [128][136] (aliased)

    const float *X, *W, *Bv; __nv_bfloat16 *Oh, *Ol; float scale;
    if (blockIdx.z == 0)      { X = X0; W = W0; Bv = B0; Oh = Oh0; Ol = Ol0; scale = 0.125f; }
    else if (blockIdx.z == 1) { X = X1; W = W1; Bv = B1; Oh = Oh1; Ol = Ol1; scale = 1.0f; }
    else                      { X = X2; W = W2; Bv = B2; Oh = Oh2; Ol = Ol2; scale = 1.0f; }

    const int tid = threadIdx.x;
    const int warp = tid >> 5, wm = warp >> 1, wn = warp & 1;
    const int m0 = blockIdx.y * 128, n0 = blockIdx.x * 128;
    const int lr = tid >> 3, lc = tid & 7;

    wmma::fragment<wmma::accumulator, 16, 16, 16, float> acc[2][4];
#pragma unroll
    for (int i = 0; i < 2; i++)
#pragma unroll
        for (int j = 0; j < 4; j++) wmma::fill_fragment(acc[i][j], 0.0f);

    for (int k0 = 0; k0 < DD; k0 += 32) {
#pragma unroll
        for (int it = 0; it < 4; it++) {
            int r = lr + it * 32;
            float4 xv = *(const float4*)(X + (size_t)(m0 + r) * DD + k0 + lc * 4);
            float4 wv = *(const float4*)(W + (size_t)(n0 + r) * DD + k0 + lc * 4);
            int sa = r * 40 + lc * 4;
            float xs[4] = {xv.x, xv.y, xv.z, xv.w};
            float ws[4] = {wv.x, wv.y, wv.z, wv.w};
#pragma unroll
            for (int j = 0; j < 4; j++) {
                __nv_bfloat16 h, l;
                split_bf(xs[j], h, l); sAh[sa + j] = h; sAl[sa + j] = l;
                split_bf(ws[j], h, l); sBh[sa + j] = h; sBl[sa + j] = l;
            }
        }
        __syncthreads();
#pragma unroll
        for (int kk = 0; kk < 32; kk += 16) {
            wmma::fragment<wmma::matrix_a, 16, 16, 16, __nv_bfloat16, wmma::row_major> ah[2], al[2];
#pragma unroll
            for (int i = 0; i < 2; i++) {
                wmma::load_matrix_sync(ah[i], sAh + (wm * 32 + i * 16) * 40 + kk, 40);
                wmma::load_matrix_sync(al[i], sAl + (wm * 32 + i * 16) * 40 + kk, 40);
            }
#pragma unroll
            for (int j = 0; j < 4; j++) {
                wmma::fragment<wmma::matrix_b, 16, 16, 16, __nv_bfloat16, wmma::col_major> bh_, bl_;
                wmma::load_matrix_sync(bh_, sBh + (wn * 64 + j * 16) * 40 + kk, 40);
                wmma::load_matrix_sync(bl_, sBl + (wn * 64 + j * 16) * 40 + kk, 40);
#pragma unroll
                for (int i = 0; i < 2; i++) {
                    wmma::mma_sync(acc[i][j], ah[i], bh_, acc[i][j]);
                    wmma::mma_sync(acc[i][j], ah[i], bl_, acc[i][j]);
                    wmma::mma_sync(acc[i][j], al[i], bh_, acc[i][j]);
                }
            }
        }
        __syncthreads();
    }

#pragma unroll
    for (int i = 0; i < 2; i++)
#pragma unroll
        for (int j = 0; j < 4; j++)
            wmma::store_matrix_sync(sC + (wm * 32 + i * 16) * 136 + wn * 64 + j * 16,
                                    acc[i][j], 136, wmma::mem_row_major);
    __syncthreads();

#pragma unroll
    for (int it = 0; it < 16; it++) {
        int idx = tid + it * 256;
        int r = idx >> 5, c4 = (idx & 31) * 4;
        float4 v = *(float4*)&sC[r * 136 + c4];
        float4 bb = *(const float4*)&Bv[n0 + c4];
        float o[4] = {(v.x + bb.x) * scale, (v.y + bb.y) * scale,
                      (v.z + bb.z) * scale, (v.w + bb.w) * scale};
        int gc = n0 + c4;
        int hh = gc >> 6, d = gc & 63;
        int gr = m0 + r;
        int b = gr >> 11, s = gr & (S - 1);
        size_t p = (((size_t)(b * H + hh)) * S + s) * HD + d;
        __nv_bfloat16 oh[4], ol[4];
#pragma unroll
        for (int j = 0; j < 4; j++) split_bf(o[j], oh[j], ol[j]);
        uint2 uh, ul;
        uh.x = pack2(oh[0], oh[1]); uh.y = pack2(oh[2], oh[3]);
        ul.x = pack2(ol[0], ol[1]); ul.y = pack2(ol[2], ol[3]);
        *(uint2*)&Oh[p] = uh;
        *(uint2*)&Ol[p] = ul;
    }
}

// ---------------------------------------------------------------------------
// Scores: 128q x 128k tile, d=64 resident. e = mask ? 0 : exp(Q'.K)
// (0.125 pre-folded into Q'). Writes e as bf16 hi/lo; atomic rowsums.
// ---------------------------------------------------------------------------
__global__ void __launch_bounds__(256, 2)
scores_wmma(const __nv_bfloat16* __restrict__ Qh, const __nv_bfloat16* __restrict__ Ql,
            const __nv_bfloat16* __restrict__ Kh, const __nv_bfloat16* __restrict__ Kl,
            const unsigned char* __restrict__ mask,
            __nv_bfloat16* __restrict__ Eh, __nv_bfloat16* __restrict__ El,
            float* __restrict__ rowsum) {
    extern __shared__ char smraw[];
    __nv_bfloat16* sQh = (__nv_bfloat16*)smraw;        // [128][72]
    __nv_bfloat16* sQl = sQh + 128 * 72;
    __nv_bfloat16* sKh = sQl + 128 * 72;
    __nv_bfloat16* sKl = sKh + 128 * 72;
    float* sC = (float*)smraw;                          // [128][136] (aliased)

    const int tid = threadIdx.x;
    const int warp = tid >> 5, wm = warp >> 1, wn = warp & 1;
    const int bh = blockIdx.z;
    const int q0 = blockIdx.y * 128, k0 = blockIdx.x * 128;
    const size_t qb = (size_t)bh * S * HD;
    const int lr = tid >> 3, lc = tid & 7;

#pragma unroll
    for (int it = 0; it < 4; it++) {
        int r = lr + it * 32;
        *(uint4*)&sQh[r * 72 + lc * 8] = *(const uint4*)&Qh[qb + (size_t)(q0 + r) * HD + lc * 8];
        *(uint4*)&sQl[r * 72 + lc * 8] = *(const uint4*)&Ql[qb + (size_t)(q0 + r) * HD + lc * 8];
        *(uint4*)&sKh[r * 72 + lc * 8] = *(const uint4*)&Kh[qb + (size_t)(k0 + r) * HD + lc * 8];
        *(uint4*)&sKl[r * 72 + lc * 8] = *(const uint4*)&Kl[qb + (size_t)(k0 + r) * HD + lc * 8];
    }
    __syncthreads();

    wmma::fragment<wmma::accumulator, 16, 16, 16, float> acc[2][4];
#pragma unroll
    for (int i = 0; i < 2; i++)
#pragma unroll
        for (int j = 0; j < 4; j++) wmma::fill_fragment(acc[i][j], 0.0f);

#pragma unroll
    for (int kk = 0; kk < 64; kk += 16) {
        wmma::fragment<wmma::matrix_a, 16, 16, 16, __nv_bfloat16, wmma::row_major> ah[2], al[2];
#pragma unroll
        for (int i = 0; i < 2; i++) {
            wmma::load_matrix_sync(ah[i], sQh + (wm * 32 + i * 16) * 72 + kk, 72);
            wmma::load_matrix_sync(al[i], sQl + (wm * 32 + i * 16) * 72 + kk, 72);
        }
#pragma unroll
        for (int j = 0; j < 4; j++) {
            wmma::fragment<wmma::matrix_b, 16, 16, 16, __nv_bfloat16, wmma::col_major> bh_, bl_;
            wmma::load_matrix_sync(bh_, sKh + (wn * 64 + j * 16) * 72 + kk, 72);
            wmma::load_matrix_sync(bl_, sKl + (wn * 64 + j * 16) * 72 + kk, 72);
#pragma unroll
            for (int i = 0; i < 2; i++) {
                wmma::mma_sync(acc[i][j], ah[i], bh_, acc[i][j]);
                wmma::mma_sync(acc[i][j], ah[i], bl_, acc[i][j]);
                wmma::mma_sync(acc[i][j], al[i], bh_, acc[i][j]);
            }
        }
    }
    __syncthreads();

#pragma unroll
    for (int i = 0; i < 2; i++)
#pragma unroll
        for (int j = 0; j < 4; j++)
            wmma::store_matrix_sync(sC + (wm * 32 + i * 16) * 136 + wn * 64 + j * 16,
                                    acc[i][j], 136, wmma::mem_row_major);
    __syncthreads();

    const unsigned char* mb = mask + (size_t)(bh & (BB - 1)) * S * S;
    const size_t eb = (size_t)bh * S * S;
#pragma unroll
    for (int it = 0; it < 16; it++) {
        int idx = tid + it * 256;
        int r = idx >> 5, c4 = (idx & 31) * 4;
        int q = q0 + r, kc = k0 + c4;
        float4 v = *(float4*)&sC[r * 136 + c4];
        uchar4 m4 = *(const uchar4*)&mb[(size_t)q * S + kc];
        float e0 = m4.x ? 0.0f : fast_exp(v.x);
        float e1 = m4.y ? 0.0f : fast_exp(v.y);
        float e2 = m4.z ? 0.0f : fast_exp(v.z);
        float e3 = m4.w ? 0.0f : fast_exp(v.w);
        __nv_bfloat16 h0, l0, h1, l1, h2, l2, h3, l3;
        split_bf(e0, h0, l0); split_bf(e1, h1, l1);
        split_bf(e2, h2, l2); split_bf(e3, h3, l3);
        uint2 uh, ul;
        uh.x = pack2(h0, h1); uh.y = pack2(h2, h3);
        ul.x = pack2(l0, l1); ul.y = pack2(l2, l3);
        size_t p = eb + (size_t)q * S + kc;
        *(uint2*)&Eh[p] = uh;
        *(uint2*)&El[p] = ul;
        float rs = e0 + e1 + e2 + e3;
#pragma unroll
        for (int o = 16; o > 0; o >>= 1) rs += __shfl_xor_sync(0xffffffffu, rs, o);
        if ((tid & 31) == 0) atomicAdd(&rowsum[bh * S + q], rs);
    }
}

// ---------------------------------------------------------------------------
// AV: a = e * (1/rowsum) -> attn output (fp32) AND re-split bf16 hi/lo for
// MMA A. ctx = a @ V via wmma, direct global store (ld=1024).
// ---------------------------------------------------------------------------
__global__ void __launch_bounds__(256, 2)
av_wmma(const __nv_bfloat16* __restrict__ Eh, const __nv_bfloat16* __restrict__ El,
        const __nv_bfloat16* __restrict__ Vh, const __nv_bfloat16* __restrict__ Vl,
        const float* __restrict__ rowsum,
        float* __restrict__ attn, float* __restrict__ ctx) {
    __shared__ __nv_bfloat16 sAh[128 * 40], sAl[128 * 40];
    __shared__ __nv_bfloat16 sVh[32 * 72], sVl[32 * 72];
    __shared__ float rr[128];

    const int tid = threadIdx.x;
    const int warp = tid >> 5, wm = warp >> 1, wn = warp & 1;
    const int bh = blockIdx.y, q0 = blockIdx.x * 128;
    const int b = bh >> 4, h = bh & 15;
    const size_t eb = (size_t)bh * S * S;
    const size_t vb = (size_t)bh * S * HD;
    float* attnb = attn + eb;
    const int lr = tid >> 3, lc = tid & 7;

    if (tid < 128) rr[tid] = 1.0f / rowsum[bh * S + q0 + tid];
    __syncthreads();

    wmma::fragment<wmma::accumulator, 16, 16, 16, float> acc[2][2];
#pragma unroll
    for (int i = 0; i < 2; i++)
#pragma unroll
        for (int j = 0; j < 2; j++) wmma::fill_fragment(acc[i][j], 0.0f);

    for (int k0 = 0; k0 < S; k0 += 32) {
#pragma unroll
        for (int it = 0; it < 4; it++) {
            int r = lr + it * 32;
            size_t p = eb + (size_t)(q0 + r) * S + k0 + lc * 4;
            uint2 uh = *(const uint2*)&Eh[p];
            uint2 ul = *(const uint2*)&El[p];
            float2 h01 = unpack2(uh.x), h23 = unpack2(uh.y);
            float2 l01 = unpack2(ul.x), l23 = unpack2(ul.y);
            float rrq = rr[r];
            float a0 = (h01.x + l01.x) * rrq;
            float a1 = (h01.y + l01.y) * rrq;
            float a2 = (h23.x + l23.x) * rrq;
            float a3 = (h23.y + l23.y) * rrq;
            *(float4*)&attnb[(size_t)(q0 + r) * S + k0 + lc * 4] = make_float4(a0, a1, a2, a3);
            __nv_bfloat16 ah0, al0, ah1, al1, ah2, al2, ah3, al3;
            split_bf(a0, ah0, al0); split_bf(a1, ah1, al1);
            split_bf(a2, ah2, al2); split_bf(a3, ah3, al3);
            uint2 sh, sl;
            sh.x = pack2(ah0, ah1); sh.y = pack2(ah2, ah3);
            sl.x = pack2(al0, al1); sl.y = pack2(al2, al3);
            *(uint2*)&sAh[r * 40 + lc * 4] = sh;
            *(uint2*)&sAl[r * 40 + lc * 4] = sl;
        }
        {
            int r = tid >> 3, c = tid & 7;
            *(uint4*)&sVh[r * 72 + c * 8] = *(const uint4*)&Vh[vb + (size_t)(k0 + r) * HD + c * 8];
            *(uint4*)&sVl[r * 72 + c * 8] = *(const uint4*)&Vl[vb + (size_t)(k0 + r) * HD + c * 8];
        }
        __syncthreads();
#pragma unroll
        for (int kk = 0; kk < 32; kk += 16) {
            wmma::fragment<wmma::matrix_a, 16, 16, 16, __nv_bfloat16, wmma::row_major> ah[2], al[2];
#pragma unroll
            for (int i = 0; i < 2; i++) {
                wmma::load_matrix_sync(ah[i], sAh + (wm * 32 + i * 16) * 40 + kk, 40);
                wmma::load_matrix_sync(al[i], sAl + (wm * 32 + i * 16) * 40 + kk, 40);
            }
#pragma unroll
            for (int j = 0; j < 2; j++) {
                wmma::fragment<wmma::matrix_b, 16, 16, 16, __nv_bfloat16, wmma::row_major> bh_, bl_;
                wmma::load_matrix_sync(bh_, sVh + kk * 72 + wn * 32 + j * 16, 72);
                wmma::load_matrix_sync(bl_, sVl + kk * 72 + wn * 32 + j * 16, 72);
#pragma unroll
                for (int i = 0; i < 2; i++) {
                    wmma::mma_sync(acc[i][j], ah[i], bh_, acc[i][j]);
                    wmma::mma_sync(acc[i][j], ah[i], bl_, acc[i][j]);
                    wmma::mma_sync(acc[i][j], al[i], bh_, acc[i][j]);
                }
            }
        }
        __syncthreads();
    }

#pragma unroll
    for (int i = 0; i < 2; i++)
#pragma unroll
        for (int j = 0; j < 2; j++) {
            int m = q0 + wm * 32 + i * 16;
            int n = wn * 32 + j * 16;
            float* p = ctx + ((size_t)b * S + m) * DD + h * HD + n;
            wmma::store_matrix_sync(p, acc[i][j], DD, wmma::mem_row_major);
        }
}

// ---------------------------------------------------------------------------
extern "C" void kernel_launch(void* const* d_in, const int* in_sizes, int n_in,
                              void* d_out, int out_size) {
    const float* query = (const float*)d_in[0];
    const float* key   = (const float*)d_in[1];
    const float* value = (const float*)d_in[2];
    const void*  mask  = d_in[3];
    const float* Wq = (const float*)d_in[4];
    const float* bq = (const float*)d_in[5];
    const float* Wk = (const float*)d_in[6];
    const float* bk = (const float*)d_in[7];
    const float* Wv = (const float*)d_in[8];
    const float* bv = (const float*)d_in[9];

    float* ctx = (float*)d_out;

    __nv_bfloat16 *qh, *ql, *kh, *kl, *vh, *vl, *eh, *el;
    float *rowsum, *attn_fallback;
    unsigned char* mu8;
    cudaGetSymbolAddress((void**)&qh, g_qh);
    cudaGetSymbolAddress((void**)&ql, g_ql);
    cudaGetSymbolAddress((void**)&kh, g_kh);
    cudaGetSymbolAddress((void**)&kl, g_kl);
    cudaGetSymbolAddress((void**)&vh, g_vh);
    cudaGetSymbolAddress((void**)&vl, g_vl);
    cudaGetSymbolAddress((void**)&eh, g_eh);
    cudaGetSymbolAddress((void**)&el, g_el);
    cudaGetSymbolAddress((void**)&mu8, g_mask_u8);
    cudaGetSymbolAddress((void**)&rowsum, g_rowsum);
    cudaGetSymbolAddress((void**)&attn_fallback, g_attn_scratch);

    const long long CTX_ELEMS  = (long long)BB * S * DD;
    const long long ATTN_ELEMS = (long long)BH * S * S;
    float* attn = ((long long)out_size >= CTX_ELEMS + ATTN_ELEMS)
                      ? (ctx + CTX_ELEMS) : attn_fallback;

    const int PROJ_SMEM   = 128 * 136 * 4;     // 69632 (covers 40960 bf16 tiles)
    const int SCORES_SMEM = 4 * 128 * 72 * 2;  // 73728 (covers 69632 staging)
    cudaFuncSetAttribute(proj_wmma, cudaFuncAttributeMaxDynamicSharedMemorySize, PROJ_SMEM);
    cudaFuncSetAttribute(scores_wmma, cudaFuncAttributeMaxDynamicSharedMemorySize, SCORES_SMEM);

    detect_mask_kernel<<<1, 256>>>((const unsigned int*)mask);
    convert_mask_kernel<<<MASK_N / 256, 256>>>(mask, mu8);
    cudaMemsetAsync(rowsum, 0, BH * S * sizeof(float));

    proj_wmma<<<dim3(DD / 128, MROWS / 128, 3), 256, PROJ_SMEM>>>(
        query, key, value, Wq, Wk, Wv, bq, bk, bv, qh, ql, kh, kl, vh, vl);

    scores_wmma<<<dim3(S / 128, S / 128, BH), 256, SCORES_SMEM>>>(
        qh, ql, kh, kl, mu8, eh, el, rowsum);

    av_wmma<<<dim3(S / 128, BH), 256>>>(eh, el, vh, vl, rowsum, attn, ctx);
}